// round 17
// baseline (speedup 1.0000x reference)
#include <cuda_runtime.h>
#include <cstdint>

#define NB_B 8192
#define LOD 60
#define LSD 120
#define AD 10
#define NB 15
#define HH 60
#define BX 64
#define BY 10
#define NT 640
#define RPT 6      // rows per thread: 60 = BY * RPT

typedef unsigned long long u64;

// ---- device scratch ----
__device__ float4 g_tmb[LOD * 7 * NB];     // (t11,t21,t12,t22) banded, k fastest

#define FMA2(acc, a, b) asm("fma.rn.f32x2 %0, %1, %2, %0;" : "+l"(acc) : "l"(a), "l"(b))
__device__ __forceinline__ float2 U2F(u64 v){ float2 r; asm("mov.b64 {%0,%1},%2;" : "=f"(r.x), "=f"(r.y) : "l"(v)); return r; }
__device__ __forceinline__ u64 F2U(float x, float y){ u64 r; asm("mov.b64 %0,{%1,%2};" : "=l"(r) : "f"(x), "f"(y)); return r; }
__device__ __forceinline__ u64 LDS64(uint32_t a){ u64 r; asm("ld.shared.b64 %0,[%1];" : "=l"(r) : "r"(a)); return r; }

// ======================= pack kernel (tiny, overlapped via PDL) =======================
__global__ void __launch_bounds__(512) pack_kernel(
    const float* __restrict__ tm11, const float* __restrict__ tm12,
    const float* __restrict__ tm21, const float* __restrict__ tm22)
{
    int idx = blockIdx.x * 512 + threadIdx.x;
    if (idx >= LOD * 7 * NB) return;
    int k = idx % NB;
    int jj = (idx / NB) % 7;
    int i = idx / (NB * 7);
    int j = i + jj - 3;
    float4 v = make_float4(0.f, 0.f, 0.f, 0.f);
    if (j >= 0 && j < LOD) {
        int off = k * LOD * LOD + i * LOD + j;
        v.x = tm11[off]; v.y = tm21[off];
        v.z = tm12[off]; v.w = tm22[off];
    }
    g_tmb[idx] = v;
}

// ======================= fused main kernel =======================
// persistent smem regions (float offsets)
#define SM_TMB   0        // 25200 floats; prep scratch first, then tmb (stage reuses tmb rows)
#define SM_MUML  25200    // float2[60][66] -> 7920
#define SM_CUCL  33120    // 7920
#define SM_CS2   41040    // 3960
#define SM_COEF  45000    // u64[15][64] -> 1920
#define SM_TC    46920    // 120
#define SM_CTL   47040    // float2 pairs -> 7920
#define SM_FLOATS 54960   // 219840 bytes

// prep scratch inside tmb region (dead before tmb load)
#define PW_WC   0         // packed float2[15][60] -> 1800
#define PW_W1   1800      // 600
#define PW_W2   2400      // duplicated float2[120][60] -> 14400
#define PW_B1   16800     // 60
#define PW_B2   16860     // 120
#define PW_BC   16980     // 15 (+pad)
#define PW_ACT  17000     // 10*66 = 660
#define PW_H    17660     // 60*66 = 3960
#define PW_LG   21620     // 15*66 = 990 -> 22610 < 25200

__device__ __forceinline__ void combine(
    u64 aXv, u64 aYv, bool diag, int jc, int x, const float* __restrict__ sm,
    float& nmu, float& nml, float& ncu, float& ncl, float& ncs)
{
    float2 X = U2F(aXv), Y = U2F(aYv);
    float t11 = X.x, t21 = X.y, t12 = Y.x, t22 = Y.y;
    if (diag) { t11 += 1.f; t22 += 1.f; }
    float2 mm = ((const float2*)(sm + SM_MUML))[jc * 66 + x];   // (mu, ml)
    float2 cc = ((const float2*)(sm + SM_CUCL))[jc * 66 + x];   // (cu, cl)
    float cs2 = sm[SM_CS2 + jc * 66 + x];
    nmu = fmaf(t11, mm.x, fmaf(t12, mm.y, nmu));
    nml = fmaf(t21, mm.x, fmaf(t22, mm.y, nml));
    ncu = fmaf(t11 * t11, cc.x, fmaf(t11 * t12, cs2, fmaf(t12 * t12, cc.y, ncu)));
    ncl = fmaf(t21 * t21, cc.x, fmaf(t21 * t22, cs2, fmaf(t22 * t22, cc.y, ncl)));
    ncs = fmaf(t21 * t11, cc.x,
          fmaf(0.5f * fmaf(t22, t11, t21 * t12), cs2,
          fmaf(t22 * t12, cc.y, ncs)));
}

template<int J0, int JN>
__device__ __forceinline__ void mix_pass(
    uint32_t tmbRow, uint32_t coefA, u64* aX, u64* aY)
{
    #pragma unroll
    for (int jj = 0; jj < JN; jj++) { aX[jj] = 0; aY[jj] = 0; }
    #pragma unroll
    for (int k = 0; k < NB; k++) {
        u64 c2 = LDS64(coefA + (uint32_t)(k * 512));
        #pragma unroll
        for (int jj = 0; jj < JN; jj++) {
            u64 vX, vY;   // (t11,t21), (t12,t22) — warp-uniform broadcast
            asm("ld.shared.v2.u64 {%0,%1},[%2];"
                : "=l"(vX), "=l"(vY)
                : "r"(tmbRow + (uint32_t)(((J0 + jj) * NB + k) * 16)));
            FMA2(aX[jj], c2, vX);
            FMA2(aY[jj], c2, vY);
        }
    }
}

__global__ void __launch_bounds__(NT, 1) acpredict_kernel(
    const float* __restrict__ post_mean, const float* __restrict__ cu_g,
    const float* __restrict__ cl_g, const float* __restrict__ cs_g,
    const float* __restrict__ action, const float* __restrict__ log_noise,
    const float* __restrict__ w_coef, const float* __restrict__ b_coef,
    const float* __restrict__ w_c1, const float* __restrict__ b_c1,
    const float* __restrict__ w_c2, const float* __restrict__ b_c2,
    float* __restrict__ out)
{
    extern __shared__ float sm[];
    const int x   = threadIdx.x;           // 0..63 : batch element
    const int y   = threadIdx.y;           // 0..9  : row group (pair of warps)
    const int tid = y * BX + x;
    const int b0  = blockIdx.x * BX;

    // ---- phase 0: load inputs + prep weights (incremental indexing) ----
    {   // post_mean: 7680 elems, 12 iters; step 640 = 5*120 + 40
        int bl = tid / LSD, d = tid - bl * LSD;
        #pragma unroll 1
        for (int r = 0; r < 12; r++) {
            float v = post_mean[(b0 + bl) * LSD + d];
            int j = (d < LOD) ? d : d - LOD;
            sm[SM_MUML + (j * 66 + bl) * 2 + (d < LOD ? 0 : 1)] = v;
            bl += 5; d += 40;
            if (d >= LSD) { d -= LSD; bl += 1; }
        }
    }
    {   // cu/cl/cs: 3840 elems, 6 iters; step 640 = 10*60 + 40
        int bl = tid / LOD, j = tid - bl * LOD;
        #pragma unroll 1
        for (int r = 0; r < 6; r++) {
            int src = (b0 + bl) * LOD + j;
            int dst = (j * 66 + bl) * 2;
            sm[SM_CUCL + dst + 0] = cu_g[src];
            sm[SM_CUCL + dst + 1] = cl_g[src];
            sm[SM_CS2 + j * 66 + bl] = 2.f * cs_g[src];
            bl += 10; j += 40;
            if (j >= LOD) { j -= LOD; bl += 1; }
        }
    }
    {   // action: exactly 640 elems = 1 per thread
        int bl = tid / AD, d = tid - bl * AD;
        sm[PW_ACT + d * 66 + bl] = action[tid + b0 * AD];
    }
    {   // w_coef: 1800 elems, 3 iters; step 640 = 5*120 + 40
        int k = tid / LSD, d = tid - k * LSD;
        int e = tid;
        #pragma unroll 1
        for (int r = 0; r < 3; r++) {
            if (e < NB * LSD) {
                int j = (d < LOD) ? d : d - LOD;
                sm[PW_WC + (k * LOD + j) * 2 + (d < LOD ? 0 : 1)] = w_coef[e];
            }
            k += 5; d += 40; e += NT;
            if (d >= LSD) { d -= LSD; k += 1; }
        }
    }
    if (tid < HH * AD) sm[PW_W1 + tid] = w_c1[tid];     // 600 < 640
    // w_c2 duplicated as (w,w) pairs — linear index, no div
    #pragma unroll 1
    for (int e = tid; e < LSD * HH; e += NT) {
        float v = w_c2[e];
        ((u64*)(sm + PW_W2))[e] = F2U(v, v);
    }
    if (tid < HH)  sm[PW_B1 + tid] = b_c1[tid];
    if (tid < LSD) sm[PW_B2 + tid] = b_c2[tid];
    if (tid < NB)  sm[PW_BC + tid] = b_coef[tid];
    if (tid < LSD) {
        float v = log_noise[tid];
        sm[SM_TC + tid] = (v < 0.f) ? __expf(v) : v + 1.f;
    }
    __syncthreads();

    // ---- phase 1: logits (batch-pair LDS.128) + hidden layer ----
    if (tid < NB * 32) {                       // 480 items, one per thread
        const int k   = tid >> 5;              // 0..14 (warp-uniform)
        const int blp = tid & 31;               // batch pair -> batches 2blp, 2blp+1
        u64 accA = 0, accB = 0;
        const u64* wcP = (const u64*)(sm + PW_WC) + k * LOD;     // warp-uniform
        const uint32_t mmA = (uint32_t)__cvta_generic_to_shared(sm + SM_MUML)
                           + (uint32_t)(blp * 16);
        #pragma unroll 4
        for (int j = 0; j < LOD; j++) {
            u64 mA, mB;    // (mu,ml) for batches 2blp and 2blp+1
            asm("ld.shared.v2.u64 {%0,%1},[%2];"
                : "=l"(mA), "=l"(mB) : "r"(mmA + (uint32_t)(j * 528)));
            FMA2(accA, wcP[j], mA);
            FMA2(accB, wcP[j], mB);
        }
        float bc = sm[PW_BC + k];
        float2 pA = U2F(accA), pB = U2F(accB);
        sm[PW_LG + k * 66 + 2 * blp]     = pA.x + pA.y + bc;
        sm[PW_LG + k * 66 + 2 * blp + 1] = pB.x + pB.y + bc;
    }
    {   // hidden layer: 3840 items, 6 iters; step 640 = 10*64
        int i = tid / BX, bl = tid - i * BX;   // bl fixed, i += 10 each iter
        #pragma unroll 1
        for (int r = 0; r < 6; r++) {
            float hv = sm[PW_B1 + i];
            #pragma unroll
            for (int d = 0; d < AD; d++)
                hv = fmaf(sm[PW_W1 + i * AD + d], sm[PW_ACT + d * 66 + bl], hv);
            sm[PW_H + i * 66 + bl] = fmaxf(hv, 0.f);
            i += 10;
        }
    }
    __syncthreads();

    // ---- phase 2: softmax (-> SM_COEF) + control MLP (x6 groups, 1 item/thread) ----
    if (tid < BX) {
        const int bl = tid;
        float mx = -1e30f;
        #pragma unroll
        for (int k = 0; k < NB; k++) mx = fmaxf(mx, sm[PW_LG + k * 66 + bl]);
        float ex[NB], sum = 0.f;
        #pragma unroll
        for (int k = 0; k < NB; k++) {
            ex[k] = __expf(sm[PW_LG + k * 66 + bl] - mx);
            sum += ex[k];
        }
        float inv = 1.f / sum;
        #pragma unroll
        for (int k = 0; k < NB; k++) {
            float c = ex[k] * inv;
            ((u64*)(sm + SM_COEF))[k * BX + bl] = F2U(c, c);
        }
    }
    // 20 channel-groups (6 channels) x 32 batch-pairs = 640 items = 1 per thread
    {
        const int g   = tid >> 5;        // 0..19 : channel group (warp-uniform)
        const int blp = tid & 31;        // batch pair 0..31
        const int c0  = g * 6;
        u64 acc[6];
        #pragma unroll
        for (int q = 0; q < 6; q++) {
            float bb = sm[PW_B2 + c0 + q];
            acc[q] = F2U(bb, bb);
        }
        const u64* w2P = (const u64*)(sm + PW_W2);               // warp-uniform dup pairs
        const u64* hP  = (const u64*)(sm + PW_H);                // h[m][2blp..2blp+1]
        #pragma unroll 4
        for (int m = 0; m < HH; m++) {
            u64 hm = hP[m * 33 + blp];
            #pragma unroll
            for (int q = 0; q < 6; q++)
                FMA2(acc[q], w2P[(c0 + q) * HH + m], hm);
        }
        #pragma unroll
        for (int q = 0; q < 6; q++)
            ((u64*)(sm + SM_CTL))[(c0 + q) * 33 + blp] = acc[q];
    }
    __syncthreads();

    // ---- phase 3: wait for pack kernel, load tmb into smem ----
    cudaGridDependencySynchronize();
    {
        float4* t4 = (float4*)sm;
        for (int e = tid; e < LOD * 7 * NB; e += NT) t4[e] = g_tmb[e];
    }
    __syncthreads();

    // ---- phase 4: mix + combine; stage per-row into own dead tmb slot ----
    const uint32_t sbase = (uint32_t)__cvta_generic_to_shared(sm);
    const uint32_t coefA = sbase + SM_COEF * 4 + (uint32_t)x * 8u;

    #pragma unroll
    for (int t = 0; t < RPT; t++) {
        const int i = y + BY * t;
        const uint32_t tmbRow = sbase + (uint32_t)(i * 7 * NB * 16);

        float nmu = 0.f, nml = 0.f, ncu = 0.f, ncl = 0.f, ncs = 0.f;
        {   // jj 0..3
            u64 aX[4], aY[4];
            mix_pass<0, 4>(tmbRow, coefA, aX, aY);
            #pragma unroll
            for (int jj = 0; jj < 4; jj++) {
                int jc = max(i + jj - 3, 0);
                combine(aX[jj], aY[jj], jj == 3, jc, x, sm, nmu, nml, ncu, ncl, ncs);
            }
        }
        {   // jj 4..6
            u64 aX[3], aY[3];
            mix_pass<4, 3>(tmbRow, coefA, aX, aY);
            #pragma unroll
            for (int jj = 0; jj < 3; jj++) {
                int jc = min(i + 1 + jj, LOD - 1);
                combine(aX[jj], aY[jj], false, jc, x, sm, nmu, nml, ncu, ncl, ncs);
            }
        }

        // pair barrier: both warps of this y done READING tmb row i
        asm volatile("bar.sync %0, 64;" :: "r"(y + 1) : "memory");

        // stage into this row's own (now dead) tmb slot: 420 floats per row
        float* stg = sm + i * 420;
        stg[0 * 64 + x] = nmu;
        stg[1 * 64 + x] = nml;
        stg[2 * 64 + x] = ncu;
        stg[3 * 64 + x] = ncl;
        stg[4 * 64 + x] = ncs;
    }
    __syncthreads();

    // ---- phase 5: coalesced stores; incremental (bl, c) indexing ----
    // stage layout: value(q, row i, batch bl) at sm[i*420 + q*64 + bl]
    {
        int bl5 = tid / 300;
        int c5  = tid - bl5 * 300;
        for (int r = 0; r < 30; r++) {
            int q = c5 / 60;
            int i = c5 - q * 60;
            float v = sm[i * 420 + q * 64 + bl5];
            int bb = b0 + bl5;
            if (c5 < 120) {
                v += sm[SM_CTL + c5 * 66 + bl5];
                out[bb * 120 + c5] = v;
            } else {
                if (c5 < 240) v += sm[SM_TC + (c5 - 120)];
                out[NB_B * 60 * q + bb * 60 + i] = v;
            }
            // advance e by NT=640 = 2*300 + 40
            bl5 += 2; c5 += 40;
            if (c5 >= 300) { c5 -= 300; bl5 += 1; }
        }
    }
}

extern "C" void kernel_launch(void* const* d_in, const int* in_sizes, int n_in,
                              void* d_out, int out_size) {
    const float* post_mean = (const float*)d_in[0];
    const float* cu        = (const float*)d_in[1];
    const float* cl        = (const float*)d_in[2];
    const float* cs        = (const float*)d_in[3];
    const float* action    = (const float*)d_in[4];
    const float* tm11      = (const float*)d_in[5];
    const float* tm12      = (const float*)d_in[6];
    const float* tm21      = (const float*)d_in[7];
    const float* tm22      = (const float*)d_in[8];
    const float* log_noise = (const float*)d_in[9];
    const float* w_coef    = (const float*)d_in[10];
    const float* b_coef    = (const float*)d_in[11];
    const float* w_c1      = (const float*)d_in[12];
    const float* b_c1      = (const float*)d_in[13];
    const float* w_c2      = (const float*)d_in[14];
    const float* b_c2      = (const float*)d_in[15];
    float* out = (float*)d_out;

    static bool attr_done = false;
    if (!attr_done) {
        cudaFuncSetAttribute(acpredict_kernel,
            cudaFuncAttributeMaxDynamicSharedMemorySize, SM_FLOATS * 4);
        attr_done = true;
    }

    // primary: tiny tmb pack
    pack_kernel<<<13, 512>>>(tm11, tm12, tm21, tm22);

    // secondary: fused main kernel with PDL (preamble overlaps pack)
    cudaLaunchConfig_t cfg = {};
    cfg.gridDim = dim3(NB_B / BX);
    cfg.blockDim = dim3(BX, BY);
    cfg.dynamicSmemBytes = SM_FLOATS * 4;
    cfg.stream = 0;
    cudaLaunchAttribute at[1];
    at[0].id = cudaLaunchAttributeProgrammaticStreamSerialization;
    at[0].val.programmaticStreamSerializationAllowed = 1;
    cfg.attrs = at;
    cfg.numAttrs = 1;
    cudaLaunchKernelEx(&cfg, acpredict_kernel,
                       post_mean, cu, cl, cs, action, log_noise,
                       w_coef, b_coef, w_c1, b_c1, w_c2, b_c2, out);
}